// round 9
// baseline (speedup 1.0000x reference)
#include <cuda_runtime.h>
#include <cuda_bf16.h>
#include <cstdint>

#define N_NODES 20000
#define R_REL   8
#define KA      2048
#define KTOT    2304
#define BK      32
#define LDTS    36              // fp32 SMEM stride (32 + 4 pad)
#define NSEG_MX (N_NODES * R_REL)
#define E_MAX   650000

// ---------------- static device scratch ----------------
__device__ float g_A[(size_t)N_NODES * KA];     // tf32-rounded aggregated feats
__device__ float g_xt[(size_t)N_NODES * 256];   // tf32-rounded x
__device__ float g_h[(size_t)N_NODES * 256];    // layer-1 activations (fp32)
__device__ float g_ht[(size_t)N_NODES * 256];   // tf32-rounded h
__device__ float g_Wt1[256 * KTOT];             // [outc][K] tf32-rounded
__device__ float g_Wt2[128 * KTOT];
__device__ int   g_cnt[NSEG_MX];
__device__ int   g_off[NSEG_MX + 1];
__device__ int   g_cur[NSEG_MX];
__device__ int   g_part[(NSEG_MX + 255) / 256];
__device__ int   g_sorted[E_MAX];
__device__ int   g_is64;

__device__ __forceinline__ int load_idx(const void* p, long long i, int is64) {
    return is64 ? (int)((const long long*)p)[i] : ((const int*)p)[i];
}
__device__ __forceinline__ float tf32r(float v) {
    uint32_t r;
    asm("cvt.rna.tf32.f32 %0, %1;" : "=r"(r) : "f"(v));
    return __uint_as_float(r);
}

// ---------------- prep kernels ----------------
__global__ void k_detect_zero(const unsigned* __restrict__ ei_words, int nwords, int nseg) {
    int i = blockIdx.x * blockDim.x + threadIdx.x;
    if (i == 0) {
        int is64 = 1;
        int lim = nwords < 256 ? nwords : 256;
        for (int j = 1; j < lim; j += 2)
            if (ei_words[j] != 0u) { is64 = 0; break; }
        g_is64 = is64;
    }
    if (i < nseg) g_cnt[i] = 0;
}

__global__ void k_count(const void* __restrict__ ei, const void* __restrict__ et, int E) {
    int e = blockIdx.x * blockDim.x + threadIdx.x;
    if (e >= E) return;
    int is64 = g_is64;
    int dst = load_idx(ei, (long long)E + e, is64);
    int r   = load_idx(et, e, is64);
    atomicAdd(&g_cnt[dst * R_REL + r], 1);
}

__global__ void k_scan1(int nseg) {
    __shared__ int sh[256];
    int b = blockIdx.x, t = threadIdx.x, i = b * 256 + t;
    int v = (i < nseg) ? g_cnt[i] : 0;
    sh[t] = v; __syncthreads();
#pragma unroll
    for (int d = 1; d < 256; d <<= 1) {
        int add = (t >= d) ? sh[t - d] : 0;
        __syncthreads();
        sh[t] += add;
        __syncthreads();
    }
    if (i < nseg) g_off[i + 1] = sh[t];
    if (t == 255) g_part[b] = sh[255];
}

__global__ void k_scan2(int nseg) {
    __shared__ int sh[256];
    int b = blockIdx.x, t = threadIdx.x, i = b * 256 + t;
    int s = 0;
    for (int j = t; j < b; j += 256) s += g_part[j];
    sh[t] = s; __syncthreads();
#pragma unroll
    for (int d = 128; d > 0; d >>= 1) { if (t < d) sh[t] += sh[t + d]; __syncthreads(); }
    int base = sh[0];
    int selfv = (i < nseg) ? g_off[i + 1] : 0;
    int prev  = (t > 0 && i < nseg) ? g_off[i] : 0;
    __syncthreads();
    if (i < nseg) {
        g_off[i + 1] = selfv + base;
        g_cur[i] = base + prev;
    }
    if (b == 0 && t == 0) g_off[0] = 0;
}

__global__ void k_scatter(const void* __restrict__ ei, const void* __restrict__ et, int E) {
    int e = blockIdx.x * blockDim.x + threadIdx.x;
    if (e >= E) return;
    int is64 = g_is64;
    int src = load_idx(ei, e, is64);
    int dst = load_idx(ei, (long long)E + e, is64);
    int r   = load_idx(et, e, is64);
    int pos = atomicAdd(&g_cur[dst * R_REL + r], 1);
    g_sorted[pos] = src;
}

// ---------------- CSR aggregation: warp per (dst,rel) segment ----------------
__global__ __launch_bounds__(256) void k_agg_csr(
    const float* __restrict__ x, float* __restrict__ A, int nseg)
{
    int w = (int)(((size_t)blockIdx.x * blockDim.x + threadIdx.x) >> 5);
    if (w >= nseg) return;
    int lane = threadIdx.x & 31;
    int beg = g_off[w], end = g_off[w + 1];
    int cnt = end - beg;

    float4 a0 = make_float4(0.f, 0.f, 0.f, 0.f);
    float4 a1 = make_float4(0.f, 0.f, 0.f, 0.f);

    for (int base = beg; base < end; base += 32) {
        int m = end - base; if (m > 32) m = 32;
        int myE = (lane < m) ? g_sorted[base + lane] : 0;
        for (int j = 0; j < m; ++j) {
            int src = __shfl_sync(0xffffffffu, myE, j);
            const float4* xs = (const float4*)(x + (size_t)src * 256 + lane * 8);
            float4 v0 = xs[0], v1 = xs[1];
            a0.x += v0.x; a0.y += v0.y; a0.z += v0.z; a0.w += v0.w;
            a1.x += v1.x; a1.y += v1.y; a1.z += v1.z; a1.w += v1.w;
        }
    }
    float s = cnt > 0 ? 1.0f / (float)cnt : 0.0f;
    float4 o0, o1;
    o0.x = tf32r(a0.x * s); o0.y = tf32r(a0.y * s);
    o0.z = tf32r(a0.z * s); o0.w = tf32r(a0.w * s);
    o1.x = tf32r(a1.x * s); o1.y = tf32r(a1.y * s);
    o1.z = tf32r(a1.z * s); o1.w = tf32r(a1.w * s);

    float* dst = A + (size_t)w * 256 + lane * 8;
    *(float4*)(dst)     = o0;
    *(float4*)(dst + 4) = o1;
}

// ---------------- weight / input conversion (tf32 rounding) ----------------
__global__ void k_wconv(const float* __restrict__ W1, const float* __restrict__ r1,
                        const float* __restrict__ W2, const float* __restrict__ r2) {
    int idx = blockIdx.x * blockDim.x + threadIdx.x;
    const int L1 = 256 * KTOT, L2 = 128 * KTOT;
    if (idx < L1) {
        int nrow = idx / KTOT, k = idx % KTOT;
        float v = (k < KA) ? W1[(size_t)k * 256 + nrow] : r1[(size_t)(k - KA) * 256 + nrow];
        g_Wt1[idx] = tf32r(v);
    } else if (idx < L1 + L2) {
        int i2 = idx - L1;
        int nrow = i2 / KTOT, k = i2 % KTOT;
        float v = (k < KA) ? W2[(size_t)k * 128 + nrow] : r2[(size_t)(k - KA) * 128 + nrow];
        g_Wt2[i2] = tf32r(v);
    }
}

__global__ void k_xconv(const float* __restrict__ x, int total) {
    int idx = blockIdx.x * blockDim.x + threadIdx.x;
    if (idx >= total) return;
    g_xt[idx] = tf32r(x[idx]);
}

// ---------------- pipelined tf32 mma.sync GEMM (3-stage, dist-2 prefetch) ----
#define MMA_TF32(C, A0, A1, A2, A3, B0, B1)                                   \
    asm volatile(                                                             \
        "mma.sync.aligned.m16n8k8.row.col.f32.tf32.tf32.f32 "                 \
        "{%0,%1,%2,%3}, {%4,%5,%6,%7}, {%8,%9}, {%0,%1,%2,%3};"               \
        : "+f"(C[0]), "+f"(C[1]), "+f"(C[2]), "+f"(C[3])                      \
        : "r"(A0), "r"(A1), "r"(A2), "r"(A3), "r"(B0), "r"(B1))

__device__ __forceinline__ uint32_t smem_u32(const void* p) {
    uint32_t a;
    asm("{ .reg .u64 t; cvta.to.shared.u64 t, %1; cvt.u32.u64 %0, t; }" : "=r"(a) : "l"(p));
    return a;
}
__device__ __forceinline__ void cpa16(uint32_t dst, const void* src) {
    asm volatile("cp.async.cg.shared.global [%0], [%1], 16;" :: "r"(dst), "l"(src));
}

#define PLANE_BYTES (128 * LDTS * 4)           // 18432
#define OFF_A 0
#define OFF_B (PLANE_BYTES)
#define STAGE_BYTES (2 * PLANE_BYTES)          // 36864
#define NSTAGE 3
#define SMEM_TOTAL (NSTAGE * STAGE_BYTES)      // 110592

__global__ __launch_bounds__(256) void k_gemm_tf32(
    const float* __restrict__ Aagg, const float* __restrict__ Xt,
    const float* __restrict__ Wt,
    const float* __restrict__ bias, float* __restrict__ out,
    float* __restrict__ H, float* __restrict__ Ht,   // layer-1 extras (or null)
    int n, int outc, int do_relu, int nsplit)
{
    extern __shared__ char smem[];
    const uint32_t sb0 = smem_u32(smem);

    const int tid  = threadIdx.x;
    const int wid  = tid >> 5;
    const int lane = tid & 31;
    const int g    = lane >> 2;
    const int t    = lane & 3;
    // L2-pairing grid encoding: twin n-blocks of the same m panel are adjacent.
    const int m0   = (blockIdx.x / nsplit) * 128;
    const int n0   = (blockIdx.x % nsplit) * 128;
    const int warpM = (wid & 3) * 32;
    const int warpN = (wid >> 2) * 64;

    // staging map: 2 threads per row, 64B each (row = 32 floats = 128B)
    const int srow  = tid >> 1;
    const int shalf = tid & 1;
    int anode = m0 + srow; if (anode >= n) anode = n - 1;
    const size_t aoffA = (size_t)anode * KA;
    const size_t aoffX = (size_t)anode * 256;
    const size_t boff  = (size_t)(n0 + srow) * KTOT;
    const uint32_t sdst = srow * (LDTS * 4) + shalf * 64;

#define STAGE(KT, STG) do {                                                    \
        int kbase_ = (KT) * BK;                                                \
        uint32_t sb_ = sb0 + (STG) * STAGE_BYTES + sdst;                       \
        const char* pa_;                                                       \
        if (kbase_ < KA)                                                       \
            pa_ = (const char*)(Aagg + aoffA + kbase_) + shalf * 64;           \
        else                                                                   \
            pa_ = (const char*)(Xt + aoffX + (kbase_ - KA)) + shalf * 64;      \
        const char* pb_ = (const char*)(Wt + boff + kbase_) + shalf * 64;      \
        cpa16(sb_ + OFF_A,      pa_);      cpa16(sb_ + OFF_A + 16, pa_ + 16);  \
        cpa16(sb_ + OFF_A + 32, pa_ + 32); cpa16(sb_ + OFF_A + 48, pa_ + 48);  \
        cpa16(sb_ + OFF_B,      pb_);      cpa16(sb_ + OFF_B + 16, pb_ + 16);  \
        cpa16(sb_ + OFF_B + 32, pb_ + 32); cpa16(sb_ + OFF_B + 48, pb_ + 48);  \
    } while (0)

    float acc[2][8][4];
#pragma unroll
    for (int mi = 0; mi < 2; ++mi)
#pragma unroll
        for (int ni = 0; ni < 8; ++ni)
#pragma unroll
            for (int c = 0; c < 4; ++c) acc[mi][ni][c] = 0.0f;

    const int KT = KTOT / BK;   // 72

    // prologue: fill stages 0,1
    STAGE(0, 0);
    asm volatile("cp.async.commit_group;");
    STAGE(1, 1);
    asm volatile("cp.async.commit_group;");

    int slot = 0;
    for (int kt = 0; kt < KT; ++kt) {
        // prefetch distance 2 (empty commit keeps group arithmetic constant)
        if (kt + 2 < KT) {
            int ps = slot + 2; if (ps >= NSTAGE) ps -= NSTAGE;
            STAGE(kt + 2, ps);
        }
        asm volatile("cp.async.commit_group;");
        asm volatile("cp.async.wait_group 2;");
        __syncthreads();

        const float* sA = (const float*)(smem + slot * STAGE_BYTES + OFF_A);
        const float* sB = (const float*)(smem + slot * STAGE_BYTES + OFF_B);

#pragma unroll
        for (int ks = 0; ks < 4; ++ks) {
            const int kk = ks * 8;
            uint32_t a[2][4];
#pragma unroll
            for (int mi = 0; mi < 2; ++mi) {
                int base0 = (warpM + mi * 16 + g) * LDTS + kk + t;
                int base1 = base0 + 8 * LDTS;
                a[mi][0] = *(const uint32_t*)&sA[base0];
                a[mi][1] = *(const uint32_t*)&sA[base1];
                a[mi][2] = *(const uint32_t*)&sA[base0 + 4];
                a[mi][3] = *(const uint32_t*)&sA[base1 + 4];
            }
#pragma unroll
            for (int ni = 0; ni < 8; ++ni) {
                int o = (warpN + ni * 8 + g) * LDTS + kk + t;
                uint32_t b0 = *(const uint32_t*)&sB[o];
                uint32_t b1 = *(const uint32_t*)&sB[o + 4];
#pragma unroll
                for (int mi = 0; mi < 2; ++mi)
                    MMA_TF32(acc[mi][ni], a[mi][0], a[mi][1], a[mi][2], a[mi][3], b0, b1);
            }
        }
        __syncthreads();
        if (++slot == NSTAGE) slot = 0;
    }

    // --- epilogue ---
#pragma unroll
    for (int mi = 0; mi < 2; ++mi) {
        int r0 = m0 + warpM + mi * 16 + g;
#pragma unroll
        for (int ni = 0; ni < 8; ++ni) {
            int c = n0 + warpN + ni * 8 + 2 * t;
            float b0 = bias[c], b1 = bias[c + 1];
            float v0 = acc[mi][ni][0] + b0;
            float v1 = acc[mi][ni][1] + b1;
            float v2 = acc[mi][ni][2] + b0;
            float v3 = acc[mi][ni][3] + b1;
            if (do_relu) {
                v0 = fmaxf(v0, 0.f); v1 = fmaxf(v1, 0.f);
                v2 = fmaxf(v2, 0.f); v3 = fmaxf(v3, 0.f);
            }
            if (r0 < n) {
                *(float2*)(out + (size_t)r0 * outc + c) = make_float2(v0, v1);
                if (H) {
                    *(float2*)(H + (size_t)r0 * 256 + c) = make_float2(v0, v1);
                    *(float2*)(Ht + (size_t)r0 * 256 + c) =
                        make_float2(tf32r(v0), tf32r(v1));
                }
            }
            if (r0 + 8 < n) {
                *(float2*)(out + (size_t)(r0 + 8) * outc + c) = make_float2(v2, v3);
                if (H) {
                    *(float2*)(H + (size_t)(r0 + 8) * 256 + c) = make_float2(v2, v3);
                    *(float2*)(Ht + (size_t)(r0 + 8) * 256 + c) =
                        make_float2(tf32r(v2), tf32r(v3));
                }
            }
        }
    }
}

// ---------------------------------------------------------------------------
extern "C" void kernel_launch(void* const* d_in, const int* in_sizes, int n_in,
                              void* d_out, int out_size)
{
    const float* x     = (const float*)d_in[0];
    const float* W1    = (const float*)d_in[1];
    const float* root1 = (const float*)d_in[2];
    const float* b1    = (const float*)d_in[3];
    const float* W2    = (const float*)d_in[4];
    const float* root2 = (const float*)d_in[5];
    const float* b2    = (const float*)d_in[6];
    const void*  ei    = d_in[7];
    const void*  et    = d_in[8];

    int E = in_sizes[8];
    int n = in_sizes[0] / 256;
    int nseg = n * R_REL;
    int sblk = (nseg + 255) / 256;

    float *A, *xt, *h, *ht, *Wt1, *Wt2;
    cudaGetSymbolAddress((void**)&A,   g_A);
    cudaGetSymbolAddress((void**)&xt,  g_xt);
    cudaGetSymbolAddress((void**)&h,   g_h);
    cudaGetSymbolAddress((void**)&ht,  g_ht);
    cudaGetSymbolAddress((void**)&Wt1, g_Wt1);
    cudaGetSymbolAddress((void**)&Wt2, g_Wt2);

    cudaFuncSetAttribute(k_gemm_tf32, cudaFuncAttributeMaxDynamicSharedMemorySize, SMEM_TOTAL);

    int mblk = (n + 127) / 128;

    // CSR build (once; shared by both layers)
    k_detect_zero<<<sblk, 256>>>((const unsigned*)ei, 2 * E, nseg);
    k_count<<<(E + 255) / 256, 256>>>(ei, et, E);
    k_scan1<<<sblk, 256>>>(nseg);
    k_scan2<<<sblk, 256>>>(nseg);
    k_scatter<<<(E + 255) / 256, 256>>>(ei, et, E);

    // ---- layer 1 ----
    k_agg_csr<<<(nseg + 7) / 8, 256>>>(x, A, nseg);
    k_wconv<<<(384 * KTOT + 255) / 256, 256>>>(W1, root1, W2, root2);
    k_xconv<<<(n * 256 + 255) / 256, 256>>>(x, n * 256);
    k_gemm_tf32<<<mblk * 2, 256, SMEM_TOTAL>>>(A, xt, Wt1, b1, h, h, ht, n, 256, 1, 2);

    // ---- layer 2 ----
    k_agg_csr<<<(nseg + 7) / 8, 256>>>(h, A, nseg);
    k_gemm_tf32<<<mblk, 256, SMEM_TOTAL>>>(A, ht, Wt2, b2, (float*)d_out,
                                           (float*)nullptr, (float*)nullptr, n, 128, 0, 1);
}

// round 10
// speedup vs baseline: 1.0289x; 1.0289x over previous
#include <cuda_runtime.h>
#include <cuda_bf16.h>
#include <cstdint>

#define N_NODES 20000
#define R_REL   8
#define KA      2048
#define KTOT    2304
#define BK      32
#define LDTS    36              // fp32 SMEM stride (32 + 4 pad)
#define NSEG_MX (N_NODES * R_REL)
#define E_MAX   650000

// ---------------- static device scratch ----------------
__device__ float g_A[(size_t)N_NODES * KA];     // tf32-rounded aggregated feats
__device__ float g_xt[(size_t)N_NODES * 256];   // tf32-rounded x
__device__ float g_h[(size_t)N_NODES * 256];    // layer-1 activations (fp32)
__device__ float g_ht[(size_t)N_NODES * 256];   // tf32-rounded h
__device__ float g_Wt1[256 * KTOT];             // [outc][K] tf32-rounded
__device__ float g_Wt2[128 * KTOT];
__device__ int   g_cnt[NSEG_MX];
__device__ int   g_off[NSEG_MX + 1];
__device__ int   g_cur[NSEG_MX];
__device__ int   g_part[(NSEG_MX + 255) / 256];
__device__ int   g_sorted[E_MAX];
__device__ int   g_is64;

__device__ __forceinline__ int load_idx(const void* p, long long i, int is64) {
    return is64 ? (int)((const long long*)p)[i] : ((const int*)p)[i];
}
__device__ __forceinline__ float tf32r(float v) {
    uint32_t r;
    asm("cvt.rna.tf32.f32 %0, %1;" : "=r"(r) : "f"(v));
    return __uint_as_float(r);
}

// ---------------- prep kernels ----------------
__global__ void k_detect_zero(const unsigned* __restrict__ ei_words, int nwords, int nseg) {
    int i = blockIdx.x * blockDim.x + threadIdx.x;
    if (i == 0) {
        int is64 = 1;
        int lim = nwords < 256 ? nwords : 256;
        for (int j = 1; j < lim; j += 2)
            if (ei_words[j] != 0u) { is64 = 0; break; }
        g_is64 = is64;
    }
    if (i < nseg) g_cnt[i] = 0;
}

__global__ void k_count(const void* __restrict__ ei, const void* __restrict__ et, int E) {
    int e = blockIdx.x * blockDim.x + threadIdx.x;
    if (e >= E) return;
    int is64 = g_is64;
    int dst = load_idx(ei, (long long)E + e, is64);
    int r   = load_idx(et, e, is64);
    atomicAdd(&g_cnt[dst * R_REL + r], 1);
}

__global__ void k_scan1(int nseg) {
    __shared__ int sh[256];
    int b = blockIdx.x, t = threadIdx.x, i = b * 256 + t;
    int v = (i < nseg) ? g_cnt[i] : 0;
    sh[t] = v; __syncthreads();
#pragma unroll
    for (int d = 1; d < 256; d <<= 1) {
        int add = (t >= d) ? sh[t - d] : 0;
        __syncthreads();
        sh[t] += add;
        __syncthreads();
    }
    if (i < nseg) g_off[i + 1] = sh[t];
    if (t == 255) g_part[b] = sh[255];
}

__global__ void k_scan2(int nseg) {
    __shared__ int sh[256];
    int b = blockIdx.x, t = threadIdx.x, i = b * 256 + t;
    int s = 0;
    for (int j = t; j < b; j += 256) s += g_part[j];
    sh[t] = s; __syncthreads();
#pragma unroll
    for (int d = 128; d > 0; d >>= 1) { if (t < d) sh[t] += sh[t + d]; __syncthreads(); }
    int base = sh[0];
    int selfv = (i < nseg) ? g_off[i + 1] : 0;
    int prev  = (t > 0 && i < nseg) ? g_off[i] : 0;
    __syncthreads();
    if (i < nseg) {
        g_off[i + 1] = selfv + base;
        g_cur[i] = base + prev;
    }
    if (b == 0 && t == 0) g_off[0] = 0;
}

__global__ void k_scatter(const void* __restrict__ ei, const void* __restrict__ et, int E) {
    int e = blockIdx.x * blockDim.x + threadIdx.x;
    if (e >= E) return;
    int is64 = g_is64;
    int src = load_idx(ei, e, is64);
    int dst = load_idx(ei, (long long)E + e, is64);
    int r   = load_idx(et, e, is64);
    int pos = atomicAdd(&g_cur[dst * R_REL + r], 1);
    g_sorted[pos] = src;
}

// ---------------- CSR aggregation: warp per (dst,rel) segment ----------------
__global__ __launch_bounds__(256) void k_agg_csr(
    const float* __restrict__ x, float* __restrict__ A, int nseg)
{
    int w = (int)(((size_t)blockIdx.x * blockDim.x + threadIdx.x) >> 5);
    if (w >= nseg) return;
    int lane = threadIdx.x & 31;
    int beg = g_off[w], end = g_off[w + 1];
    int cnt = end - beg;

    float4 a0 = make_float4(0.f, 0.f, 0.f, 0.f);
    float4 a1 = make_float4(0.f, 0.f, 0.f, 0.f);

    for (int base = beg; base < end; base += 32) {
        int m = end - base; if (m > 32) m = 32;
        int myE = (lane < m) ? g_sorted[base + lane] : 0;
        for (int j = 0; j < m; ++j) {
            int src = __shfl_sync(0xffffffffu, myE, j);
            const float4* xs = (const float4*)(x + (size_t)src * 256 + lane * 8);
            float4 v0 = xs[0], v1 = xs[1];
            a0.x += v0.x; a0.y += v0.y; a0.z += v0.z; a0.w += v0.w;
            a1.x += v1.x; a1.y += v1.y; a1.z += v1.z; a1.w += v1.w;
        }
    }
    float s = cnt > 0 ? 1.0f / (float)cnt : 0.0f;
    float4 o0, o1;
    o0.x = tf32r(a0.x * s); o0.y = tf32r(a0.y * s);
    o0.z = tf32r(a0.z * s); o0.w = tf32r(a0.w * s);
    o1.x = tf32r(a1.x * s); o1.y = tf32r(a1.y * s);
    o1.z = tf32r(a1.z * s); o1.w = tf32r(a1.w * s);

    float* dst = A + (size_t)w * 256 + lane * 8;
    *(float4*)(dst)     = o0;
    *(float4*)(dst + 4) = o1;
}

// ---------------- weight / input conversion (tf32 rounding) ----------------
__global__ void k_wconv(const float* __restrict__ W1, const float* __restrict__ r1,
                        const float* __restrict__ W2, const float* __restrict__ r2) {
    int idx = blockIdx.x * blockDim.x + threadIdx.x;
    const int L1 = 256 * KTOT, L2 = 128 * KTOT;
    if (idx < L1) {
        int nrow = idx / KTOT, k = idx % KTOT;
        float v = (k < KA) ? W1[(size_t)k * 256 + nrow] : r1[(size_t)(k - KA) * 256 + nrow];
        g_Wt1[idx] = tf32r(v);
    } else if (idx < L1 + L2) {
        int i2 = idx - L1;
        int nrow = i2 / KTOT, k = i2 % KTOT;
        float v = (k < KA) ? W2[(size_t)k * 128 + nrow] : r2[(size_t)(k - KA) * 128 + nrow];
        g_Wt2[i2] = tf32r(v);
    }
}

__global__ void k_xconv(const float* __restrict__ x, int total) {
    int idx = blockIdx.x * blockDim.x + threadIdx.x;
    if (idx >= total) return;
    g_xt[idx] = tf32r(x[idx]);
}

// ---------------- pipelined tf32 mma.sync GEMM (3-stage, 2 CTAs/SM) ----------
#define MMA_TF32(C, A0, A1, A2, A3, B0, B1)                                   \
    asm volatile(                                                             \
        "mma.sync.aligned.m16n8k8.row.col.f32.tf32.tf32.f32 "                 \
        "{%0,%1,%2,%3}, {%4,%5,%6,%7}, {%8,%9}, {%0,%1,%2,%3};"               \
        : "+f"(C[0]), "+f"(C[1]), "+f"(C[2]), "+f"(C[3])                      \
        : "r"(A0), "r"(A1), "r"(A2), "r"(A3), "r"(B0), "r"(B1))

__device__ __forceinline__ uint32_t smem_u32(const void* p) {
    uint32_t a;
    asm("{ .reg .u64 t; cvta.to.shared.u64 t, %1; cvt.u32.u64 %0, t; }" : "=r"(a) : "l"(p));
    return a;
}
__device__ __forceinline__ void cpa16(uint32_t dst, const void* src) {
    asm volatile("cp.async.cg.shared.global [%0], [%1], 16;" :: "r"(dst), "l"(src));
}

#define PLANE_BYTES (128 * LDTS * 4)           // 18432
#define OFF_A 0
#define OFF_B (PLANE_BYTES)
#define STAGE_BYTES (2 * PLANE_BYTES)          // 36864
#define NSTAGE 3
#define SMEM_TOTAL (NSTAGE * STAGE_BYTES)      // 110592 -> 2 CTAs/SM = 221184

__global__ __launch_bounds__(256, 2) void k_gemm_tf32(
    const float* __restrict__ Aagg, const float* __restrict__ Xt,
    const float* __restrict__ Wt,
    const float* __restrict__ bias, float* __restrict__ out,
    float* __restrict__ H, float* __restrict__ Ht,   // layer-1 extras (or null)
    int n, int outc, int do_relu, int nsplit)
{
    extern __shared__ char smem[];
    const uint32_t sb0 = smem_u32(smem);

    const int tid  = threadIdx.x;
    const int wid  = tid >> 5;
    const int lane = tid & 31;
    const int g    = lane >> 2;
    const int t    = lane & 3;
    // L2-pairing grid encoding: twin n-blocks of the same m panel are adjacent.
    const int m0   = (blockIdx.x / nsplit) * 128;
    const int n0   = (blockIdx.x % nsplit) * 128;
    const int warpM = (wid & 3) * 32;
    const int warpN = (wid >> 2) * 64;

    // staging map: 2 threads per row, 64B each (row = 32 floats = 128B)
    const int srow  = tid >> 1;
    const int shalf = tid & 1;
    int anode = m0 + srow; if (anode >= n) anode = n - 1;
    const size_t aoffA = (size_t)anode * KA;
    const size_t aoffX = (size_t)anode * 256;
    const size_t boff  = (size_t)(n0 + srow) * KTOT;
    const uint32_t sdst = srow * (LDTS * 4) + shalf * 64;

#define STAGE(KT, STG) do {                                                    \
        int kbase_ = (KT) * BK;                                                \
        uint32_t sb_ = sb0 + (STG) * STAGE_BYTES + sdst;                       \
        const char* pa_;                                                       \
        if (kbase_ < KA)                                                       \
            pa_ = (const char*)(Aagg + aoffA + kbase_) + shalf * 64;           \
        else                                                                   \
            pa_ = (const char*)(Xt + aoffX + (kbase_ - KA)) + shalf * 64;      \
        const char* pb_ = (const char*)(Wt + boff + kbase_) + shalf * 64;      \
        cpa16(sb_ + OFF_A,      pa_);      cpa16(sb_ + OFF_A + 16, pa_ + 16);  \
        cpa16(sb_ + OFF_A + 32, pa_ + 32); cpa16(sb_ + OFF_A + 48, pa_ + 48);  \
        cpa16(sb_ + OFF_B,      pb_);      cpa16(sb_ + OFF_B + 16, pb_ + 16);  \
        cpa16(sb_ + OFF_B + 32, pb_ + 32); cpa16(sb_ + OFF_B + 48, pb_ + 48);  \
    } while (0)

    float acc[2][8][4];
#pragma unroll
    for (int mi = 0; mi < 2; ++mi)
#pragma unroll
        for (int ni = 0; ni < 8; ++ni)
#pragma unroll
            for (int c = 0; c < 4; ++c) acc[mi][ni][c] = 0.0f;

    const int KT = KTOT / BK;   // 72

    // prologue: fill stages 0,1
    STAGE(0, 0);
    asm volatile("cp.async.commit_group;");
    STAGE(1, 1);
    asm volatile("cp.async.commit_group;");

    int slot = 0;
    for (int kt = 0; kt < KT; ++kt) {
        // prefetch distance 2 (empty commit keeps group arithmetic constant)
        if (kt + 2 < KT) {
            int ps = slot + 2; if (ps >= NSTAGE) ps -= NSTAGE;
            STAGE(kt + 2, ps);
        }
        asm volatile("cp.async.commit_group;");
        asm volatile("cp.async.wait_group 2;");
        __syncthreads();

        const float* sA = (const float*)(smem + slot * STAGE_BYTES + OFF_A);
        const float* sB = (const float*)(smem + slot * STAGE_BYTES + OFF_B);

#pragma unroll
        for (int ks = 0; ks < 4; ++ks) {
            const int kk = ks * 8;
            uint32_t a[2][4];
#pragma unroll
            for (int mi = 0; mi < 2; ++mi) {
                int base0 = (warpM + mi * 16 + g) * LDTS + kk + t;
                int base1 = base0 + 8 * LDTS;
                a[mi][0] = *(const uint32_t*)&sA[base0];
                a[mi][1] = *(const uint32_t*)&sA[base1];
                a[mi][2] = *(const uint32_t*)&sA[base0 + 4];
                a[mi][3] = *(const uint32_t*)&sA[base1 + 4];
            }
#pragma unroll
            for (int ni = 0; ni < 8; ++ni) {
                int o = (warpN + ni * 8 + g) * LDTS + kk + t;
                uint32_t b0 = *(const uint32_t*)&sB[o];
                uint32_t b1 = *(const uint32_t*)&sB[o + 4];
#pragma unroll
                for (int mi = 0; mi < 2; ++mi)
                    MMA_TF32(acc[mi][ni], a[mi][0], a[mi][1], a[mi][2], a[mi][3], b0, b1);
            }
        }
        __syncthreads();
        if (++slot == NSTAGE) slot = 0;
    }

    // --- epilogue ---
#pragma unroll
    for (int mi = 0; mi < 2; ++mi) {
        int r0 = m0 + warpM + mi * 16 + g;
#pragma unroll
        for (int ni = 0; ni < 8; ++ni) {
            int c = n0 + warpN + ni * 8 + 2 * t;
            float b0 = bias[c], b1 = bias[c + 1];
            float v0 = acc[mi][ni][0] + b0;
            float v1 = acc[mi][ni][1] + b1;
            float v2 = acc[mi][ni][2] + b0;
            float v3 = acc[mi][ni][3] + b1;
            if (do_relu) {
                v0 = fmaxf(v0, 0.f); v1 = fmaxf(v1, 0.f);
                v2 = fmaxf(v2, 0.f); v3 = fmaxf(v3, 0.f);
            }
            if (r0 < n) {
                *(float2*)(out + (size_t)r0 * outc + c) = make_float2(v0, v1);
                if (H) {
                    *(float2*)(H + (size_t)r0 * 256 + c) = make_float2(v0, v1);
                    *(float2*)(Ht + (size_t)r0 * 256 + c) =
                        make_float2(tf32r(v0), tf32r(v1));
                }
            }
            if (r0 + 8 < n) {
                *(float2*)(out + (size_t)(r0 + 8) * outc + c) = make_float2(v2, v3);
                if (H) {
                    *(float2*)(H + (size_t)(r0 + 8) * 256 + c) = make_float2(v2, v3);
                    *(float2*)(Ht + (size_t)(r0 + 8) * 256 + c) =
                        make_float2(tf32r(v2), tf32r(v3));
                }
            }
        }
    }
}

// ---------------------------------------------------------------------------
extern "C" void kernel_launch(void* const* d_in, const int* in_sizes, int n_in,
                              void* d_out, int out_size)
{
    const float* x     = (const float*)d_in[0];
    const float* W1    = (const float*)d_in[1];
    const float* root1 = (const float*)d_in[2];
    const float* b1    = (const float*)d_in[3];
    const float* W2    = (const float*)d_in[4];
    const float* root2 = (const float*)d_in[5];
    const float* b2    = (const float*)d_in[6];
    const void*  ei    = d_in[7];
    const void*  et    = d_in[8];

    int E = in_sizes[8];
    int n = in_sizes[0] / 256;
    int nseg = n * R_REL;
    int sblk = (nseg + 255) / 256;

    float *A, *xt, *h, *ht, *Wt1, *Wt2;
    cudaGetSymbolAddress((void**)&A,   g_A);
    cudaGetSymbolAddress((void**)&xt,  g_xt);
    cudaGetSymbolAddress((void**)&h,   g_h);
    cudaGetSymbolAddress((void**)&ht,  g_ht);
    cudaGetSymbolAddress((void**)&Wt1, g_Wt1);
    cudaGetSymbolAddress((void**)&Wt2, g_Wt2);

    cudaFuncSetAttribute(k_gemm_tf32, cudaFuncAttributeMaxDynamicSharedMemorySize, SMEM_TOTAL);

    int mblk = (n + 127) / 128;

    // CSR build (once; shared by both layers)
    k_detect_zero<<<sblk, 256>>>((const unsigned*)ei, 2 * E, nseg);
    k_count<<<(E + 255) / 256, 256>>>(ei, et, E);
    k_scan1<<<sblk, 256>>>(nseg);
    k_scan2<<<sblk, 256>>>(nseg);
    k_scatter<<<(E + 255) / 256, 256>>>(ei, et, E);

    // ---- layer 1 ----
    k_agg_csr<<<(nseg + 7) / 8, 256>>>(x, A, nseg);
    k_wconv<<<(384 * KTOT + 255) / 256, 256>>>(W1, root1, W2, root2);
    k_xconv<<<(n * 256 + 255) / 256, 256>>>(x, n * 256);
    k_gemm_tf32<<<mblk * 2, 256, SMEM_TOTAL>>>(A, xt, Wt1, b1, h, h, ht, n, 256, 1, 2);

    // ---- layer 2 ----
    k_agg_csr<<<(nseg + 7) / 8, 256>>>(h, A, nseg);
    k_gemm_tf32<<<mblk, 256, SMEM_TOTAL>>>(A, ht, Wt2, b2, (float*)d_out,
                                           (float*)nullptr, (float*)nullptr, n, 128, 0, 1);
}